// round 1
// baseline (speedup 1.0000x reference)
#include <cuda_runtime.h>
#include <math.h>

#define B_  2
#define S_  2048
#define D_  768
#define H_  12
#define HD_ 64

// Scratch: Q/K/V in [B,H,S,hd] layout (12.6 MB each, static device allocs are allowed)
__device__ float g_q[B_*H_*S_*HD_];
__device__ float g_k[B_*H_*S_*HD_];
__device__ float g_v[B_*H_*S_*HD_];

// ---------------------------------------------------------------------------
// QKV projection GEMM: out = v1 @ W + bias, written head-split.
// grid = (D/64 = 12 head-tiles, (B*S)/64 = 64 row-tiles, 3 for {Q,K,V})
// block = 256 threads, 64x64 tile, BK=16, 4x4 per thread.
// ---------------------------------------------------------------------------
__global__ __launch_bounds__(256)
void qkv_gemm_kernel(const float* __restrict__ A,
                     const float* __restrict__ Wq, const float* __restrict__ bq,
                     const float* __restrict__ Wk, const float* __restrict__ bk,
                     const float* __restrict__ Wv, const float* __restrict__ bv)
{
    const float* W; const float* bias; float* out;
    switch (blockIdx.z) {
        case 0:  W = Wq; bias = bq; out = g_q; break;
        case 1:  W = Wk; bias = bk; out = g_k; break;
        default: W = Wv; bias = bv; out = g_v; break;
    }

    __shared__ float As[16][68];   // [k][m], padded
    __shared__ float Bs[16][68];   // [k][n], padded

    const int tid = threadIdx.x;
    const int tx = tid & 15;       // 16 col groups
    const int ty = tid >> 4;       // 16 row groups
    const int rowBase = blockIdx.y * 64;
    const int h = blockIdx.x;
    const int colBase = h * 64;

    float acc[4][4];
    #pragma unroll
    for (int i = 0; i < 4; i++)
        #pragma unroll
        for (int j = 0; j < 4; j++) acc[i][j] = 0.f;

    const int a_k = tid & 15, a_m = tid >> 4;   // A loader: 4 passes of 16 rows
    const int b_n = tid & 63, b_k = tid >> 6;   // B loader: 4 passes of 4 k-rows

    for (int k0 = 0; k0 < D_; k0 += 16) {
        #pragma unroll
        for (int p = 0; p < 4; p++) {
            As[a_k][a_m + p*16] = A[(size_t)(rowBase + a_m + p*16) * D_ + k0 + a_k];
            Bs[b_k + p*4][b_n]  = W[(size_t)(k0 + b_k + p*4) * D_ + colBase + b_n];
        }
        __syncthreads();

        #pragma unroll
        for (int kk = 0; kk < 16; kk++) {
            float a[4], b[4];
            #pragma unroll
            for (int i = 0; i < 4; i++) a[i] = As[kk][ty*4 + i];
            #pragma unroll
            for (int j = 0; j < 4; j++) b[j] = Bs[kk][tx*4 + j];
            #pragma unroll
            for (int i = 0; i < 4; i++)
                #pragma unroll
                for (int j = 0; j < 4; j++)
                    acc[i][j] += a[i] * b[j];
        }
        __syncthreads();
    }

    #pragma unroll
    for (int i = 0; i < 4; i++) {
        const int row = rowBase + ty*4 + i;
        const int b   = row >> 11;        // row / 2048
        const int s   = row & (S_ - 1);
        float* orow = out + ((size_t)(b*H_ + h)*S_ + s) * HD_;
        #pragma unroll
        for (int j = 0; j < 4; j++) {
            const int d = tx*4 + j;
            orow[d] = acc[i][j] + bias[colBase + d];
        }
    }
}

// ---------------------------------------------------------------------------
// Flash attention: one thread per query row, online softmax.
// grid = (S/128 = 16, B*H = 24), block = 128 threads.
// K/V tiles of 64 keys staged in shared memory.
// ---------------------------------------------------------------------------
__global__ __launch_bounds__(128, 2)
void attn_kernel(const float* __restrict__ mask, float* __restrict__ out)
{
    const int bh = blockIdx.y;
    const int b  = bh / H_;
    const int h  = bh % H_;
    const int qs = blockIdx.x * 128 + threadIdx.x;   // query index in [0, S)

    const float* Q = g_q + (size_t)bh * S_ * HD_;
    const float* K = g_k + (size_t)bh * S_ * HD_;
    const float* V = g_v + (size_t)bh * S_ * HD_;
    const float* mrow = mask + (size_t)b * S_;       // v1_mask[b,0,0,:]

    __shared__ float Ks[64][HD_];
    __shared__ float Vs[64][HD_];
    __shared__ float Ms[64];

    // Load q row, fold in 1/sqrt(hd) = 0.125
    float q[HD_];
    {
        const float4* q4 = (const float4*)(Q + (size_t)qs * HD_);
        #pragma unroll
        for (int i = 0; i < HD_/4; i++) {
            float4 t = q4[i];
            q[4*i+0] = t.x * 0.125f;
            q[4*i+1] = t.y * 0.125f;
            q[4*i+2] = t.z * 0.125f;
            q[4*i+3] = t.w * 0.125f;
        }
    }

    float m = -INFINITY, l = 0.f;
    float acc[HD_];
    #pragma unroll
    for (int d = 0; d < HD_; d++) acc[d] = 0.f;

    for (int t0 = 0; t0 < S_; t0 += 64) {
        __syncthreads();   // previous iteration's reads complete
        // Cooperative tile load: 64*64 floats = 1024 float4 per tile, 128 threads
        {
            const float4* K4 = (const float4*)(K + (size_t)t0 * HD_);
            const float4* V4 = (const float4*)(V + (size_t)t0 * HD_);
            float4* Ks4 = (float4*)&Ks[0][0];
            float4* Vs4 = (float4*)&Vs[0][0];
            #pragma unroll
            for (int p = 0; p < 8; p++) {
                const int i = threadIdx.x + p * 128;
                Ks4[i] = K4[i];
                Vs4[i] = V4[i];
            }
            if (threadIdx.x < 64) Ms[threadIdx.x] = mrow[t0 + threadIdx.x];
        }
        __syncthreads();

        for (int j = 0; j < 64; j++) {
            float s = 0.f;
            #pragma unroll
            for (int d = 0; d < HD_; d++) s += q[d] * Ks[j][d];
            s += Ms[j];

            if (s > m) {   // lazy rescale: rare after warm-up
                const float corr = __expf(m - s);
                l *= corr;
                #pragma unroll
                for (int d = 0; d < HD_; d++) acc[d] *= corr;
                m = s;
            }
            const float p = __expf(s - m);
            l += p;
            #pragma unroll
            for (int d = 0; d < HD_; d++) acc[d] += p * Vs[j][d];
        }
    }

    const float inv = 1.f / l;
    float* orow = out + ((size_t)(b * S_ + qs)) * D_ + h * HD_;
    #pragma unroll
    for (int d = 0; d < HD_; d++) orow[d] = acc[d] * inv;
}

// ---------------------------------------------------------------------------
extern "C" void kernel_launch(void* const* d_in, const int* in_sizes, int n_in,
                              void* d_out, int out_size)
{
    const float* v1   = (const float*)d_in[0];
    const float* mask = (const float*)d_in[1];
    const float* Wq   = (const float*)d_in[2];
    const float* bq   = (const float*)d_in[3];
    const float* Wk   = (const float*)d_in[4];
    const float* bk   = (const float*)d_in[5];
    const float* Wv   = (const float*)d_in[6];
    const float* bv   = (const float*)d_in[7];
    float* out = (float*)d_out;

    dim3 g1(D_ / 64, (B_ * S_) / 64, 3);
    qkv_gemm_kernel<<<g1, 256>>>(v1, Wq, bq, Wk, bk, Wv, bv);

    dim3 g2(S_ / 128, B_ * H_);
    attn_kernel<<<g2, 128>>>(mask, out);
}

// round 4
// speedup vs baseline: 6.4323x; 6.4323x over previous
#include <cuda_runtime.h>
#include <math.h>
#include <stdint.h>

#define B_  2
#define S_  2048
#define D_  768
#define H_  12
#define HD_ 64
#define LOG2E 1.44269504f

// Q/K/V scratch in [B,H,S,hd] layout
__device__ float g_q[B_*H_*S_*HD_];
__device__ float g_k[B_*H_*S_*HD_];
__device__ float g_v[B_*H_*S_*HD_];

// ---------------------------------------------------------------------------
// helpers
// ---------------------------------------------------------------------------
__device__ __forceinline__ uint32_t f2tf32(float x) {
    uint32_t r;
    asm("cvt.rna.tf32.f32 %0, %1;" : "=r"(r) : "f"(x));
    return r;
}
__device__ __forceinline__ uint32_t fbits(float x) { return __float_as_uint(x); }

__device__ __forceinline__ float ex2(float x) {
    float r;
    asm("ex2.approx.f32 %0, %1;" : "=f"(r) : "f"(x));
    return r;
}

__device__ __forceinline__ void mma_tf32(float (&d)[4], const uint32_t (&a)[4],
                                         const uint32_t (&b)[2], const float (&c)[4]) {
    asm volatile(
        "mma.sync.aligned.m16n8k8.row.col.f32.tf32.tf32.f32 "
        "{%0,%1,%2,%3}, {%4,%5,%6,%7}, {%8,%9}, {%10,%11,%12,%13};\n"
        : "=f"(d[0]), "=f"(d[1]), "=f"(d[2]), "=f"(d[3])
        : "r"(a[0]), "r"(a[1]), "r"(a[2]), "r"(a[3]),
          "r"(b[0]), "r"(b[1]),
          "f"(c[0]), "f"(c[1]), "f"(c[2]), "f"(c[3]));
}

// Route a C-fragment column pair (pa=col 2t, pb=col 2t+1 of an 8-col tile)
// into A-fragment columns t and t+4 of the same 8-col k-chunk.
__device__ __forceinline__ void pfrag(float pa, float pb, int lane, float& x, float& y) {
    const int t = lane & 3;
    const int base = lane & ~3;
    const int s1 = base | (t >> 1);
    const int s2 = base | ((t >> 1) + 2);
    float v0 = __shfl_sync(0xffffffffu, pa, s1);
    float v1 = __shfl_sync(0xffffffffu, pb, s1);
    float w0 = __shfl_sync(0xffffffffu, pa, s2);
    float w1 = __shfl_sync(0xffffffffu, pb, s2);
    x = (t & 1) ? v1 : v0;   // P[row][8kc + t]
    y = (t & 1) ? w1 : w0;   // P[row][8kc + t + 4]
}

// ---------------------------------------------------------------------------
// QKV projection GEMM (tf32 mma): out = v1 @ W + b, head-split write.
// grid = (12 heads, 4096/128 = 32 row tiles, 3 {Q,K,V}); block = 256 (8 warps)
// Block tile 128x64, K-step 32. Warp tile 32x32 (warp grid 4x2).
// ---------------------------------------------------------------------------
__global__ __launch_bounds__(256, 2)
void qkv_mma_kernel(const float* __restrict__ A,
                    const float* __restrict__ Wq, const float* __restrict__ bq,
                    const float* __restrict__ Wk, const float* __restrict__ bk,
                    const float* __restrict__ Wv, const float* __restrict__ bv)
{
    const float* W; const float* bias; float* out;
    switch (blockIdx.z) {
        case 0:  W = Wq; bias = bq; out = g_q; break;
        case 1:  W = Wk; bias = bk; out = g_k; break;
        default: W = Wv; bias = bv; out = g_v; break;
    }

    __shared__ float As[128][36];   // [m][k], stride 36 (=4 mod 32): A-frag conflict-free
    __shared__ float Bs[32][72];    // [k][n], stride 72 (=8 mod 32): B-frag conflict-free

    const int tid  = threadIdx.x;
    const int w    = tid >> 5;
    const int lane = tid & 31;
    const int g    = lane >> 2;
    const int t    = lane & 3;
    const int wm   = w & 3;          // 4 m-tiles of 32
    const int wn   = w >> 2;         // 2 n-tiles of 32
    const int rowBase = blockIdx.y * 128;
    const int h       = blockIdx.x;
    const int colBase = h * 64;

    float acc[2][4][4];
    #pragma unroll
    for (int mt = 0; mt < 2; mt++)
        #pragma unroll
        for (int nt = 0; nt < 4; nt++)
            #pragma unroll
            for (int i = 0; i < 4; i++) acc[mt][nt][i] = 0.f;

    const int ar = tid >> 3, ac = (tid & 7) * 4;    // A loader: 32 rows/pass x 4
    const int br = tid >> 4, bc = (tid & 15) * 4;   // B loader: 16 rows/pass x 2

    for (int k0 = 0; k0 < D_; k0 += 32) {
        __syncthreads();
        #pragma unroll
        for (int p = 0; p < 4; p++) {
            float4 v = *(const float4*)&A[(size_t)(rowBase + ar + p*32) * D_ + k0 + ac];
            float* d = &As[ar + p*32][ac];
            d[0] = __uint_as_float(f2tf32(v.x));
            d[1] = __uint_as_float(f2tf32(v.y));
            d[2] = __uint_as_float(f2tf32(v.z));
            d[3] = __uint_as_float(f2tf32(v.w));
        }
        #pragma unroll
        for (int p = 0; p < 2; p++) {
            float4 v = *(const float4*)&W[(size_t)(k0 + br + p*16) * D_ + colBase + bc];
            float* d = &Bs[br + p*16][bc];
            d[0] = __uint_as_float(f2tf32(v.x));
            d[1] = __uint_as_float(f2tf32(v.y));
            d[2] = __uint_as_float(f2tf32(v.z));
            d[3] = __uint_as_float(f2tf32(v.w));
        }
        __syncthreads();

        #pragma unroll
        for (int kc = 0; kc < 4; kc++) {
            uint32_t af[2][4];
            #pragma unroll
            for (int mt = 0; mt < 2; mt++) {
                const int r = wm*32 + mt*16;
                af[mt][0] = fbits(As[r + g    ][kc*8 + t    ]);
                af[mt][1] = fbits(As[r + g + 8][kc*8 + t    ]);
                af[mt][2] = fbits(As[r + g    ][kc*8 + t + 4]);
                af[mt][3] = fbits(As[r + g + 8][kc*8 + t + 4]);
            }
            #pragma unroll
            for (int nt = 0; nt < 4; nt++) {
                uint32_t bf[2];
                bf[0] = fbits(Bs[kc*8 + t    ][wn*32 + nt*8 + g]);
                bf[1] = fbits(Bs[kc*8 + t + 4][wn*32 + nt*8 + g]);
                mma_tf32(acc[0][nt], af[0], bf, acc[0][nt]);
                mma_tf32(acc[1][nt], af[1], bf, acc[1][nt]);
            }
        }
    }

    // Epilogue: bias add + head-split store into [B,H,S,hd]
    #pragma unroll
    for (int mt = 0; mt < 2; mt++) {
        #pragma unroll
        for (int half = 0; half < 2; half++) {
            const int row = rowBase + wm*32 + mt*16 + g + half*8;
            const int b   = row >> 11;
            const int s   = row & (S_ - 1);
            float* orow = out + ((size_t)(b*H_ + h) * S_ + s) * HD_;
            #pragma unroll
            for (int nt = 0; nt < 4; nt++) {
                const int d = wn*32 + nt*8 + 2*t;
                float2 v;
                v.x = acc[mt][nt][half*2 + 0] + bias[colBase + d];
                v.y = acc[mt][nt][half*2 + 1] + bias[colBase + d + 1];
                *(float2*)&orow[d] = v;
            }
        }
    }
}

// ---------------------------------------------------------------------------
// Flash attention (tf32 mma): block = 256 thr (8 warps), 128 queries/block,
// warp owns 16 query rows. Key tiles of 64 staged in smem.
// grid = (S/128 = 16, B*H = 24)
// ---------------------------------------------------------------------------
__global__ __launch_bounds__(256, 1)
void attn_mma_kernel(const float* __restrict__ mask, float* __restrict__ out)
{
    __shared__ float Ks[64][68];   // [key][d], stride 68 (=4 mod 32)
    __shared__ float Vs[64][72];   // [key][d], stride 72 (=8 mod 32)
    __shared__ float Ms[64];

    const int tid  = threadIdx.x;
    const int w    = tid >> 5;
    const int lane = tid & 31;
    const int g    = lane >> 2;
    const int t    = lane & 3;

    const int bh = blockIdx.y;
    const int b  = bh / H_;
    const int h  = bh % H_;
    const int qBase = blockIdx.x * 128 + w * 16;

    const float* Qg = g_q + (size_t)bh * S_ * HD_;
    const float* Kg = g_k + (size_t)bh * S_ * HD_;
    const float* Vg = g_v + (size_t)bh * S_ * HD_;
    const float* mrow = mask + (size_t)b * S_;

    const float qscale = 0.125f * LOG2E;   // 1/sqrt(64) * log2(e)

    // Q fragments (reused across all key tiles): 8 k-chunks x 4 regs
    uint32_t qf[8][4];
    {
        const float* q0 = Qg + (size_t)(qBase + g)     * HD_;
        const float* q1 = Qg + (size_t)(qBase + g + 8) * HD_;
        #pragma unroll
        for (int kc = 0; kc < 8; kc++) {
            qf[kc][0] = f2tf32(q0[8*kc + t    ] * qscale);
            qf[kc][1] = f2tf32(q1[8*kc + t    ] * qscale);
            qf[kc][2] = f2tf32(q0[8*kc + t + 4] * qscale);
            qf[kc][3] = f2tf32(q1[8*kc + t + 4] * qscale);
        }
    }

    float o[8][4];
    #pragma unroll
    for (int dt = 0; dt < 8; dt++)
        #pragma unroll
        for (int i = 0; i < 4; i++) o[dt][i] = 0.f;

    float m0 = -INFINITY, m1 = -INFINITY, l0 = 0.f, l1 = 0.f;

    const int lr  = tid & 63;        // tile row this thread loads
    const int seg = tid >> 6;        // 16-float segment

    for (int t0 = 0; t0 < S_; t0 += 64) {
        __syncthreads();
        {
            const float4* krow = (const float4*)(Kg + (size_t)(t0 + lr) * HD_) + seg*4;
            const float4* vrow = (const float4*)(Vg + (size_t)(t0 + lr) * HD_) + seg*4;
            float* kd = &Ks[lr][seg*16];
            float* vd = &Vs[lr][seg*16];
            #pragma unroll
            for (int i = 0; i < 4; i++) {
                float4 kv = krow[i];
                kd[4*i+0] = __uint_as_float(f2tf32(kv.x));
                kd[4*i+1] = __uint_as_float(f2tf32(kv.y));
                kd[4*i+2] = __uint_as_float(f2tf32(kv.z));
                kd[4*i+3] = __uint_as_float(f2tf32(kv.w));
                float4 vv = vrow[i];
                vd[4*i+0] = __uint_as_float(f2tf32(vv.x));
                vd[4*i+1] = __uint_as_float(f2tf32(vv.y));
                vd[4*i+2] = __uint_as_float(f2tf32(vv.z));
                vd[4*i+3] = __uint_as_float(f2tf32(vv.w));
            }
            if (tid < 64) Ms[tid] = mrow[t0 + tid] * LOG2E;
        }
        __syncthreads();

        // ---- scores S = (Q*scale) @ K^T + mask  (already in log2 domain) ----
        float s[8][4];
        #pragma unroll
        for (int nt = 0; nt < 8; nt++) {
            #pragma unroll
            for (int i = 0; i < 4; i++) s[nt][i] = 0.f;
            #pragma unroll
            for (int kc = 0; kc < 8; kc++) {
                uint32_t bf[2];
                bf[0] = fbits(Ks[nt*8 + g][kc*8 + t    ]);
                bf[1] = fbits(Ks[nt*8 + g][kc*8 + t + 4]);
                mma_tf32(s[nt], qf[kc], bf, s[nt]);
            }
            const float mk0 = Ms[nt*8 + 2*t];
            const float mk1 = Ms[nt*8 + 2*t + 1];
            s[nt][0] += mk0;  s[nt][1] += mk1;
            s[nt][2] += mk0;  s[nt][3] += mk1;
        }

        // ---- online softmax (log2 domain) ----
        float mx0 = -INFINITY, mx1 = -INFINITY;
        #pragma unroll
        for (int nt = 0; nt < 8; nt++) {
            mx0 = fmaxf(mx0, fmaxf(s[nt][0], s[nt][1]));
            mx1 = fmaxf(mx1, fmaxf(s[nt][2], s[nt][3]));
        }
        mx0 = fmaxf(mx0, __shfl_xor_sync(0xffffffffu, mx0, 1));
        mx0 = fmaxf(mx0, __shfl_xor_sync(0xffffffffu, mx0, 2));
        mx1 = fmaxf(mx1, __shfl_xor_sync(0xffffffffu, mx1, 1));
        mx1 = fmaxf(mx1, __shfl_xor_sync(0xffffffffu, mx1, 2));

        const float nm0 = fmaxf(m0, mx0);
        const float nm1 = fmaxf(m1, mx1);
        const float c0 = ex2(m0 - nm0);
        const float c1 = ex2(m1 - nm1);
        m0 = nm0; m1 = nm1;

        float sum0 = 0.f, sum1 = 0.f;
        #pragma unroll
        for (int nt = 0; nt < 8; nt++) {
            s[nt][0] = ex2(s[nt][0] - nm0);
            s[nt][1] = ex2(s[nt][1] - nm0);
            s[nt][2] = ex2(s[nt][2] - nm1);
            s[nt][3] = ex2(s[nt][3] - nm1);
            sum0 += s[nt][0] + s[nt][1];
            sum1 += s[nt][2] + s[nt][3];
        }
        sum0 += __shfl_xor_sync(0xffffffffu, sum0, 1);
        sum0 += __shfl_xor_sync(0xffffffffu, sum0, 2);
        sum1 += __shfl_xor_sync(0xffffffffu, sum1, 1);
        sum1 += __shfl_xor_sync(0xffffffffu, sum1, 2);
        l0 = l0 * c0 + sum0;
        l1 = l1 * c1 + sum1;

        #pragma unroll
        for (int dt = 0; dt < 8; dt++) {
            o[dt][0] *= c0;  o[dt][1] *= c0;
            o[dt][2] *= c1;  o[dt][3] *= c1;
        }

        // ---- O += P @ V ----
        #pragma unroll
        for (int kc = 0; kc < 8; kc++) {
            float x0, y0, x1, y1;
            pfrag(s[kc][0], s[kc][1], lane, x0, y0);   // row g
            pfrag(s[kc][2], s[kc][3], lane, x1, y1);   // row g+8
            uint32_t a[4];
            a[0] = f2tf32(x0);
            a[1] = f2tf32(x1);
            a[2] = f2tf32(y0);
            a[3] = f2tf32(y1);
            #pragma unroll
            for (int dt = 0; dt < 8; dt++) {
                uint32_t bf[2];
                bf[0] = fbits(Vs[kc*8 + t    ][dt*8 + g]);
                bf[1] = fbits(Vs[kc*8 + t + 4][dt*8 + g]);
                mma_tf32(o[dt], a, bf, o[dt]);
            }
        }
    }

    // ---- epilogue: normalize + merge heads into [B,S,D] ----
    const float inv0 = 1.f / l0;
    const float inv1 = 1.f / l1;
    const int q0 = qBase + g;
    const int q1 = q0 + 8;
    float* orow0 = out + ((size_t)(b * S_ + q0)) * D_ + h * HD_;
    float* orow1 = out + ((size_t)(b * S_ + q1)) * D_ + h * HD_;
    #pragma unroll
    for (int dt = 0; dt < 8; dt++) {
        const int d = dt*8 + 2*t;
        float2 v0; v0.x = o[dt][0] * inv0; v0.y = o[dt][1] * inv0;
        float2 v1; v1.x = o[dt][2] * inv1; v1.y = o[dt][3] * inv1;
        *(float2*)&orow0[d] = v0;
        *(float2*)&orow1[d] = v1;
    }
}

// ---------------------------------------------------------------------------
extern "C" void kernel_launch(void* const* d_in, const int* in_sizes, int n_in,
                              void* d_out, int out_size)
{
    const float* v1   = (const float*)d_in[0];
    const float* mask = (const float*)d_in[1];
    const float* Wq   = (const float*)d_in[2];
    const float* bq   = (const float*)d_in[3];
    const float* Wk   = (const float*)d_in[4];
    const float* bk   = (const float*)d_in[5];
    const float* Wv   = (const float*)d_in[6];
    const float* bv   = (const float*)d_in[7];
    float* out = (float*)d_out;

    dim3 g1(H_, (B_ * S_) / 128, 3);
    qkv_mma_kernel<<<g1, 256>>>(v1, Wq, bq, Wk, bk, Wv, bv);

    dim3 g2(S_ / 128, B_ * H_);
    attn_mma_kernel<<<g2, 256>>>(mask, out);
}